// round 7
// baseline (speedup 1.0000x reference)
#include <cuda_runtime.h>
#include <cuda_fp16.h>
#include <cstdint>
#include <cstddef>

// Problem constants (fixed for this problem; M derived at launch)
#define KDIM 4096
#define NDIM 11008
#define MMAX 8192
#define BM 128
#define BN 128
#define BK 64
#define SA_STRIDE 72    // 64 + 8 halves pad -> 144B row stride (conflict-free ldmatrix)
#define SB_STRIDE 136   // 128 + 8 halves pad -> 272B row stride (conflict-free ldmatrix)

// fp16 scratch: dequantized weights (scale folded), K-major [K][N]; fp16 copy of x.
static __device__ __half g_W[(size_t)KDIM * NDIM];   // 90.2 MB
static __device__ __half g_X[(size_t)MMAX * KDIM];   // 67.1 MB

// ---------------------------------------------------------------------------
// Phase 0: convert x (float32 transport of fp16 values) -> fp16 g_X. Lossless.
// ---------------------------------------------------------------------------
__global__ void convert_x_kernel(const float* __restrict__ x, long long n) {
    long long i = ((long long)blockIdx.x * blockDim.x + threadIdx.x) * 8;
    if (i + 8 <= n) {
        float4 a = *reinterpret_cast<const float4*>(x + i);
        float4 b = *reinterpret_cast<const float4*>(x + i + 4);
        __half2 h[4];
        h[0] = __floats2half2_rn(a.x, a.y);
        h[1] = __floats2half2_rn(a.z, a.w);
        h[2] = __floats2half2_rn(b.x, b.y);
        h[3] = __floats2half2_rn(b.z, b.w);
        *reinterpret_cast<uint4*>(&g_X[i]) = *reinterpret_cast<uint4*>(h);
    }
}

// ---------------------------------------------------------------------------
// Phase 1: dequantize packed ternary weights -> fp16 g_W, scale folded in.
// packed_weight: int32 [K/16][N], code j at bits 2j; w = (code-1)*scale[k/128][n].
// scales arrive as float32 (lossless transport of fp16) -> convert back to fp16
// so the multiply rounds exactly like the reference's fp16 dequant.
// Magic trick: half(0x6400|c) == 1024+c exactly; hsub2(.,1025) is exact.
// Block: 16 kp-rows (256 k) x 64 n-cols. SMEM transpose for coalesced output.
// ---------------------------------------------------------------------------
__global__ void dequant_kernel(const int32_t* __restrict__ pw,
                               const float* __restrict__ scales) {
    __shared__ __half sw[256][72];   // 36,864 B; row stride 144B (16B-aligned)
    const int n0  = blockIdx.x * 64;
    const int kp0 = blockIdx.y * 16;
    const int t   = threadIdx.x;
    const int nl  = (t & 31) * 2;    // local n (even)
    const int r0  = t >> 5;          // 0..7
    const __half2 k1025 = __float2half2_rn(1025.0f);

#pragma unroll
    for (int rr = r0; rr < 16; rr += 8) {
        const int kp = kp0 + rr;
        const int n  = n0 + nl;
        const int32_t va = pw[(size_t)kp * NDIM + n];
        const int32_t vb = pw[(size_t)kp * NDIM + n + 1];
        const int g = kp >> 3;  // k-group = (kp*16)/128
        const __half2 s2 = __floats2half2_rn(scales[(size_t)g * NDIM + n],
                                             scales[(size_t)g * NDIM + n + 1]);
#pragma unroll
        for (int j = 0; j < 16; j++) {
            uint32_t raw = 0x64006400u
                         | ((uint32_t)(va >> (2 * j)) & 3u)
                         | (((uint32_t)(vb >> (2 * j)) & 3u) << 16);
            __half2 h = __hmul2(__hsub2(*reinterpret_cast<__half2*>(&raw), k1025), s2);
            *reinterpret_cast<__half2*>(&sw[rr * 16 + j][nl]) = h;
        }
    }
    __syncthreads();

    // Coalesced 16B writes: 256 rows x 64 halves = 2048 uint4 chunks.
#pragma unroll
    for (int i = t; i < 2048; i += 256) {
        const int row = i >> 3, c = i & 7;
        *reinterpret_cast<uint4*>(&g_W[(size_t)(kp0 * 16 + row) * NDIM + n0 + c * 8]) =
            *reinterpret_cast<const uint4*>(&sw[row][c * 8]);
    }
}

// ---------------------------------------------------------------------------
// Phase 2: fp16 GEMM with fp32 accumulation.
// C_f32[M][N] = float( half( acc_f32(g_X * g_W) ) + half(bias) )
// matching the reference's rounding order; output written as float32.
// ---------------------------------------------------------------------------
#define CP_ASYNC16(dst, src) \
    asm volatile("cp.async.cg.shared.global [%0], [%1], 16;\n" :: "r"(dst), "l"(src))

__global__ __launch_bounds__(256, 2) void gemm_kernel(
    const float* __restrict__ bias, float* __restrict__ C, int M)
{
    extern __shared__ __half smem[];
    __half* sA = smem;                        // [2][BM][SA_STRIDE]
    __half* sB = smem + 2 * BM * SA_STRIDE;   // [2][BK][SB_STRIDE]

    const int tiles_n = NDIM / BN;            // 86
    const int tiles_m = M / BM;

    // GROUP_M=8 rasterization for L2 reuse of A across N-tiles.
    const int pid = blockIdx.x;
    const int GROUPM = 8;
    const int per_group = GROUPM * tiles_n;
    const int gid = pid / per_group;
    const int first_m = gid * GROUPM;
    const int gsz = min(GROUPM, tiles_m - first_m);
    const int pm = first_m + (pid % per_group) % gsz;
    const int pn = (pid % per_group) / gsz;

    const int m0 = pm * BM, n0 = pn * BN;
    const int tid  = threadIdx.x;
    const int lane = tid & 31;
    const int warp = tid >> 5;
    const int wr = warp >> 1;   // 0..3 (M)
    const int wc = warp & 1;    // 0..1 (N)

    float acc[2][8][4];
#pragma unroll
    for (int a = 0; a < 2; a++)
#pragma unroll
        for (int b = 0; b < 8; b++)
#pragma unroll
            for (int c = 0; c < 4; c++) acc[a][b][c] = 0.f;

    const uint32_t sA_base = (uint32_t)__cvta_generic_to_shared(sA);
    const uint32_t sB_base = (uint32_t)__cvta_generic_to_shared(sB);

    // Per-thread gmem->smem chunk coordinates (16B chunks).
    const int a_row = tid >> 3;            // + 32 per iter
    const int a_c   = (tid & 7) * 8;
    const int b_row = tid >> 4;            // + 16 per iter
    const int b_c   = (tid & 15) * 8;

    const __half* Ag = g_X + (size_t)(m0 + a_row) * KDIM + a_c;
    const __half* Bg = g_W + (size_t)b_row * NDIM + n0 + b_c;

    auto load_tiles = [&](int stage, int kt) {
        uint32_t da = sA_base + (uint32_t)(stage * BM * SA_STRIDE + a_row * SA_STRIDE + a_c) * 2;
        const __half* ga = Ag + kt * BK;
#pragma unroll
        for (int i = 0; i < 4; i++) {
            CP_ASYNC16(da, ga);
            da += 32 * SA_STRIDE * 2;
            ga += (size_t)32 * KDIM;
        }
        uint32_t db = sB_base + (uint32_t)(stage * BK * SB_STRIDE + b_row * SB_STRIDE + b_c) * 2;
        const __half* gb = Bg + (size_t)kt * BK * NDIM;
#pragma unroll
        for (int i = 0; i < 4; i++) {
            CP_ASYNC16(db, gb);
            db += 16 * SB_STRIDE * 2;
            gb += (size_t)16 * NDIM;
        }
        asm volatile("cp.async.commit_group;\n");
    };

    auto compute_tile = [&](int stage) {
        const uint32_t pa = sA_base + (uint32_t)(stage * BM * SA_STRIDE) * 2;
        const uint32_t pb = sB_base + (uint32_t)(stage * BK * SB_STRIDE) * 2;
        const int ar    = wr * 32 + (lane & 7) + ((lane >> 3) & 1) * 8;  // + mi*16
        const int acoff = ((lane >> 4) & 1) * 8;                         // + ks*16
        const int bkr   = (lane & 7) + ((lane >> 3) & 1) * 8;            // + ks*16
        const int bnc   = wc * 64 + ((lane >> 4) & 1) * 8;               // + ng*16
#pragma unroll
        for (int ks = 0; ks < 4; ks++) {
            uint32_t af[2][4];
#pragma unroll
            for (int mi = 0; mi < 2; mi++) {
                const uint32_t addr = pa +
                    (uint32_t)((ar + mi * 16) * SA_STRIDE + ks * 16 + acoff) * 2;
                asm volatile("ldmatrix.sync.aligned.m8n8.x4.shared.b16 {%0,%1,%2,%3}, [%4];\n"
                    : "=r"(af[mi][0]), "=r"(af[mi][1]), "=r"(af[mi][2]), "=r"(af[mi][3])
                    : "r"(addr));
            }
            uint32_t bf[8][2];
#pragma unroll
            for (int ng = 0; ng < 4; ng++) {
                const uint32_t addr = pb +
                    (uint32_t)((ks * 16 + bkr) * SB_STRIDE + bnc + ng * 16) * 2;
                uint32_t r0, r1, r2, r3;
                asm volatile("ldmatrix.sync.aligned.m8n8.x4.trans.shared.b16 {%0,%1,%2,%3}, [%4];\n"
                    : "=r"(r0), "=r"(r1), "=r"(r2), "=r"(r3) : "r"(addr));
                bf[2 * ng][0] = r0; bf[2 * ng][1] = r1;
                bf[2 * ng + 1][0] = r2; bf[2 * ng + 1][1] = r3;
            }
#pragma unroll
            for (int mi = 0; mi < 2; mi++)
#pragma unroll
                for (int ni = 0; ni < 8; ni++) {
                    asm volatile(
                        "mma.sync.aligned.m16n8k16.row.col.f32.f16.f16.f32 "
                        "{%0,%1,%2,%3}, {%4,%5,%6,%7}, {%8,%9}, {%0,%1,%2,%3};\n"
                        : "+f"(acc[mi][ni][0]), "+f"(acc[mi][ni][1]),
                          "+f"(acc[mi][ni][2]), "+f"(acc[mi][ni][3])
                        : "r"(af[mi][0]), "r"(af[mi][1]), "r"(af[mi][2]), "r"(af[mi][3]),
                          "r"(bf[ni][0]), "r"(bf[ni][1]));
                }
        }
    };

    const int KT = KDIM / BK;  // 64
    load_tiles(0, 0);
    for (int kt = 0; kt < KT; kt++) {
        if (kt + 1 < KT) {
            load_tiles((kt + 1) & 1, kt + 1);
            asm volatile("cp.async.wait_group 1;\n");
        } else {
            asm volatile("cp.async.wait_group 0;\n");
        }
        __syncthreads();
        compute_tile(kt & 1);
        __syncthreads();
    }

    // Epilogue: half(acc) + half(bias) in fp16 (reference rounding order),
    // then widen to float32 for the output buffer.
#pragma unroll
    for (int mi = 0; mi < 2; mi++) {
        const int row = m0 + wr * 32 + mi * 16 + (lane >> 2);
#pragma unroll
        for (int ni = 0; ni < 8; ni++) {
            const int col = n0 + wc * 64 + ni * 8 + (lane & 3) * 2;
            const float2 bf32 = *reinterpret_cast<const float2*>(bias + col);
            const __half2 bv = __floats2half2_rn(bf32.x, bf32.y);
            __half2 v0 = __hadd2(__floats2half2_rn(acc[mi][ni][0], acc[mi][ni][1]), bv);
            __half2 v1 = __hadd2(__floats2half2_rn(acc[mi][ni][2], acc[mi][ni][3]), bv);
            float2 o0 = __half22float2(v0);
            float2 o1 = __half22float2(v1);
            *reinterpret_cast<float2*>(C + (size_t)row * NDIM + col) = o0;
            *reinterpret_cast<float2*>(C + (size_t)(row + 8) * NDIM + col) = o1;
        }
    }
}

// ---------------------------------------------------------------------------
extern "C" void kernel_launch(void* const* d_in, const int* in_sizes, int n_in,
                              void* d_out, int out_size) {
    const float*   x      = (const float*)d_in[0];     // fp32 transport of fp16 x
    const int32_t* pw     = (const int32_t*)d_in[1];
    const float*   scales = (const float*)d_in[2];     // fp32 transport of fp16 scales
    const float*   bias   = (const float*)d_in[3];     // fp32 transport of fp16 bias
    float*         out    = (float*)d_out;             // fp32 output
    const int M = in_sizes[0] / KDIM;                  // 8192 for (2,4096,4096)

    // Phase 0: x -> fp16.
    const long long nx = (long long)M * KDIM;
    convert_x_kernel<<<(int)((nx / 8 + 255) / 256), 256>>>(x, nx);

    // Phase 1: dequantize weights into g_W.
    dequant_kernel<<<dim3(NDIM / 64, KDIM / 256), 256>>>(pw, scales);

    // Phase 2: GEMM.
    const int smem_bytes = (2 * BM * SA_STRIDE + 2 * BK * SB_STRIDE) * (int)sizeof(__half); // 71680
    cudaFuncSetAttribute(gemm_kernel, cudaFuncAttributeMaxDynamicSharedMemorySize, smem_bytes);
    const int grid = (M / BM) * (NDIM / BN);
    gemm_kernel<<<grid, 256, smem_bytes>>>(bias, out, M);
}

// round 9
// speedup vs baseline: 1.2733x; 1.2733x over previous
#include <cuda_runtime.h>
#include <cuda_fp16.h>
#include <cstdint>
#include <cstddef>

// Problem constants (fixed for this problem; M derived at launch)
#define KDIM 4096
#define NDIM 11008
#define MMAX 8192
#define BM 128
#define BN 256
#define BK 64
#define STAGES 4
#define KT (KDIM / BK)        // 64
#define SA_STRIDE 72          // 64+8 halves -> 144B row stride (conflict-free ldmatrix)
#define SB_STRIDE 264         // 256+8 halves -> 528B row stride (528%128==16, same rotation)
#define A_STG (BM * SA_STRIDE)   // halves per A stage
#define B_STG (BK * SB_STRIDE)   // halves per B stage

// fp16 scratch: dequantized weights (scale folded), K-major [K][N]; fp16 copy of x.
static __device__ __half g_W[(size_t)KDIM * NDIM];   // 90.2 MB
static __device__ __half g_X[(size_t)MMAX * KDIM];   // 67.1 MB

// ---------------------------------------------------------------------------
// Phase 0: x (fp32 transport of fp16) -> fp16 g_X. Lossless.
// ---------------------------------------------------------------------------
__global__ void convert_x_kernel(const float* __restrict__ x, long long n) {
    long long i = ((long long)blockIdx.x * blockDim.x + threadIdx.x) * 8;
    if (i + 8 <= n) {
        float4 a = *reinterpret_cast<const float4*>(x + i);
        float4 b = *reinterpret_cast<const float4*>(x + i + 4);
        __half2 h[4];
        h[0] = __floats2half2_rn(a.x, a.y);
        h[1] = __floats2half2_rn(a.z, a.w);
        h[2] = __floats2half2_rn(b.x, b.y);
        h[3] = __floats2half2_rn(b.z, b.w);
        *reinterpret_cast<uint4*>(&g_X[i]) = *reinterpret_cast<uint4*>(h);
    }
}

// ---------------------------------------------------------------------------
// Phase 1: dequantize packed ternary -> fp16 g_W[k][n], scale folded (proven).
// half(0x6400|c)=1024+c exact; hsub2(.,1025) exact; hmul2 by fp16 scale exact
// for ternary -> bit-identical to reference dequant.
// ---------------------------------------------------------------------------
__global__ void dequant_kernel(const int32_t* __restrict__ pw,
                               const float* __restrict__ scales) {
    __shared__ __half sw[256][72];
    const int n0  = blockIdx.x * 64;
    const int kp0 = blockIdx.y * 16;
    const int t   = threadIdx.x;
    const int nl  = (t & 31) * 2;
    const int r0  = t >> 5;
    const __half2 k1025 = __float2half2_rn(1025.0f);

#pragma unroll
    for (int rr = r0; rr < 16; rr += 8) {
        const int kp = kp0 + rr;
        const int n  = n0 + nl;
        const int32_t va = pw[(size_t)kp * NDIM + n];
        const int32_t vb = pw[(size_t)kp * NDIM + n + 1];
        const int g = kp >> 3;
        const __half2 s2 = __floats2half2_rn(scales[(size_t)g * NDIM + n],
                                             scales[(size_t)g * NDIM + n + 1]);
#pragma unroll
        for (int j = 0; j < 16; j++) {
            uint32_t raw = 0x64006400u
                         | ((uint32_t)(va >> (2 * j)) & 3u)
                         | (((uint32_t)(vb >> (2 * j)) & 3u) << 16);
            __half2 h = __hmul2(__hsub2(*reinterpret_cast<__half2*>(&raw), k1025), s2);
            *reinterpret_cast<__half2*>(&sw[rr * 16 + j][nl]) = h;
        }
    }
    __syncthreads();

#pragma unroll
    for (int i = t; i < 2048; i += 256) {
        const int row = i >> 3, c = i & 7;
        *reinterpret_cast<uint4*>(&g_W[(size_t)(kp0 * 16 + row) * NDIM + n0 + c * 8]) =
            *reinterpret_cast<const uint4*>(&sw[row][c * 8]);
    }
}

// ---------------------------------------------------------------------------
// Phase 2: fp16 GEMM, fp32 accumulation, multi-stage cp.async + reg pipeline.
// C_f32 = float( half(acc) + half(bias) ), reference rounding order.
// ---------------------------------------------------------------------------
#define CP_ASYNC16(dst, src) \
    asm volatile("cp.async.cg.shared.global [%0], [%1], 16;\n" :: "r"(dst), "l"(src))

__global__ __launch_bounds__(256, 1) void gemm_kernel(
    const float* __restrict__ bias, float* __restrict__ C, int M)
{
    extern __shared__ __half smem[];
    __half* sA = smem;                      // [STAGES][BM][SA_STRIDE]
    __half* sB = smem + STAGES * A_STG;     // [STAGES][BK][SB_STRIDE]

    const int tiles_n = NDIM / BN;          // 43
    const int tiles_m = M / BM;             // 64

    // GROUP_M=16 rasterization: B re-read from DRAM only tiles_m/16 = 4 times.
    const int pid = blockIdx.x;
    const int GROUPM = 16;
    const int per_group = GROUPM * tiles_n;
    const int gid = pid / per_group;
    const int first_m = gid * GROUPM;
    const int gsz = min(GROUPM, tiles_m - first_m);
    const int rr  = pid % per_group;
    const int m0 = (first_m + rr % gsz) * BM;
    const int n0 = (rr / gsz) * BN;

    const int tid  = threadIdx.x;
    const int lane = tid & 31;
    const int warp = tid >> 5;
    const int wr = warp & 1;     // 0..1 -> 64-row slice
    const int wc = warp >> 1;    // 0..3 -> 64-col slice

    float acc[4][8][4];
#pragma unroll
    for (int a = 0; a < 4; a++)
#pragma unroll
        for (int b = 0; b < 8; b++)
#pragma unroll
            for (int c = 0; c < 4; c++) acc[a][b][c] = 0.f;

    const uint32_t sA_base = (uint32_t)__cvta_generic_to_shared(sA);
    const uint32_t sB_base = (uint32_t)__cvta_generic_to_shared(sB);

    // gmem->smem 16B-chunk coordinates.
    const int a_row = tid >> 3;           // +32/iter (4 iters)
    const int a_c   = (tid & 7) * 8;
    const int b_row = tid >> 5;           // +8/iter (8 iters)
    const int b_c   = (tid & 31) * 8;

    const __half* Ag = g_X + (size_t)(m0 + a_row) * KDIM + a_c;
    const __half* Bg = g_W + (size_t)b_row * NDIM + n0 + b_c;

    auto load_stage = [&](int stage, int kt) {
        uint32_t da = sA_base + (uint32_t)(stage * A_STG + a_row * SA_STRIDE + a_c) * 2;
        const __half* ga = Ag + kt * BK;
#pragma unroll
        for (int i = 0; i < 4; i++) {
            CP_ASYNC16(da, ga);
            da += 32 * SA_STRIDE * 2;
            ga += (size_t)32 * KDIM;
        }
        uint32_t db = sB_base + (uint32_t)(stage * B_STG + b_row * SB_STRIDE + b_c) * 2;
        const __half* gb = Bg + (size_t)kt * BK * NDIM;
#pragma unroll
        for (int i = 0; i < 8; i++) {
            CP_ASYNC16(db, gb);
            db += 8 * SB_STRIDE * 2;
            gb += (size_t)8 * NDIM;
        }
        asm volatile("cp.async.commit_group;\n");
    };

    // ldmatrix lane-address components (round-7-proven mapping, widened tiles).
    const int lrow  = (lane & 7) + ((lane >> 3) & 1) * 8;   // A row within 16
    const int acoff = ((lane >> 4) & 1) * 8;                // A k-offset within 16
    const int bkr   = (lane & 7) + ((lane >> 3) & 1) * 8;   // B k-row within 16
    const int bnc   = wc * 64 + ((lane >> 4) & 1) * 8;      // B n-offset

    uint32_t fa[2][4][4], fb[2][8][2];

    auto ldsm = [&](int stage, int ks, int buf) {
        const uint32_t pa = sA_base + (uint32_t)(stage * A_STG) * 2;
        const uint32_t pb = sB_base + (uint32_t)(stage * B_STG) * 2;
#pragma unroll
        for (int mi = 0; mi < 4; mi++) {
            const uint32_t addr = pa +
                (uint32_t)((wr * 64 + mi * 16 + lrow) * SA_STRIDE + ks * 16 + acoff) * 2;
            asm volatile("ldmatrix.sync.aligned.m8n8.x4.shared.b16 {%0,%1,%2,%3}, [%4];\n"
                : "=r"(fa[buf][mi][0]), "=r"(fa[buf][mi][1]),
                  "=r"(fa[buf][mi][2]), "=r"(fa[buf][mi][3])
                : "r"(addr));
        }
#pragma unroll
        for (int ng = 0; ng < 4; ng++) {
            const uint32_t addr = pb +
                (uint32_t)((ks * 16 + bkr) * SB_STRIDE + bnc + ng * 16) * 2;
            uint32_t r0, r1, r2, r3;
            asm volatile("ldmatrix.sync.aligned.m8n8.x4.trans.shared.b16 {%0,%1,%2,%3}, [%4];\n"
                : "=r"(r0), "=r"(r1), "=r"(r2), "=r"(r3) : "r"(addr));
            fb[buf][2 * ng][0] = r0;     fb[buf][2 * ng][1] = r1;
            fb[buf][2 * ng + 1][0] = r2; fb[buf][2 * ng + 1][1] = r3;
        }
    };

    auto mma_all = [&](int buf) {
#pragma unroll
        for (int mi = 0; mi < 4; mi++)
#pragma unroll
            for (int ni = 0; ni < 8; ni++) {
                asm volatile(
                    "mma.sync.aligned.m16n8k16.row.col.f32.f16.f16.f32 "
                    "{%0,%1,%2,%3}, {%4,%5,%6,%7}, {%8,%9}, {%0,%1,%2,%3};\n"
                    : "+f"(acc[mi][ni][0]), "+f"(acc[mi][ni][1]),
                      "+f"(acc[mi][ni][2]), "+f"(acc[mi][ni][3])
                    : "r"(fa[buf][mi][0]), "r"(fa[buf][mi][1]),
                      "r"(fa[buf][mi][2]), "r"(fa[buf][mi][3]),
                      "r"(fb[buf][ni][0]), "r"(fb[buf][ni][1]));
            }
    };

    // Prologue: fill STAGES-1 stages, wait for stage 0, prime fragments.
#pragma unroll
    for (int s = 0; s < STAGES - 1; s++) load_stage(s, s);
    asm volatile("cp.async.wait_group %0;\n" :: "n"(STAGES - 2) : "memory");
    __syncthreads();
    ldsm(0, 0, 0);

    for (int kt = 0; kt < KT; kt++) {
        const int stage = kt & (STAGES - 1);
#pragma unroll
        for (int ks = 0; ks < 4; ks++) {
            const int cur = ks & 1, nxt = cur ^ 1;
            if (ks == 0) {
                if (kt + STAGES - 1 < KT)
                    load_stage((kt + STAGES - 1) & (STAGES - 1), kt + STAGES - 1);
                else
                    asm volatile("cp.async.commit_group;\n");  // keep group count fixed
            }
            if (ks < 3) {
                ldsm(stage, ks + 1, nxt);
            } else {
                asm volatile("cp.async.wait_group %0;\n" :: "n"(STAGES - 2) : "memory");
                __syncthreads();
                if (kt + 1 < KT) ldsm((kt + 1) & (STAGES - 1), 0, nxt);
            }
            mma_all(cur);
        }
    }

    // Epilogue: half(acc) + half(bias) in fp16 (reference rounding), widen to fp32.
#pragma unroll
    for (int mi = 0; mi < 4; mi++) {
        const int row = m0 + wr * 64 + mi * 16 + (lane >> 2);
#pragma unroll
        for (int ni = 0; ni < 8; ni++) {
            const int col = n0 + wc * 64 + ni * 8 + (lane & 3) * 2;
            const float2 bf32 = *reinterpret_cast<const float2*>(bias + col);
            const __half2 bv = __floats2half2_rn(bf32.x, bf32.y);
            __half2 v0 = __hadd2(__floats2half2_rn(acc[mi][ni][0], acc[mi][ni][1]), bv);
            __half2 v1 = __hadd2(__floats2half2_rn(acc[mi][ni][2], acc[mi][ni][3]), bv);
            float2 o0 = __half22float2(v0);
            float2 o1 = __half22float2(v1);
            *reinterpret_cast<float2*>(C + (size_t)row * NDIM + col) = o0;
            *reinterpret_cast<float2*>(C + (size_t)(row + 8) * NDIM + col) = o1;
        }
    }
}

// ---------------------------------------------------------------------------
extern "C" void kernel_launch(void* const* d_in, const int* in_sizes, int n_in,
                              void* d_out, int out_size) {
    const float*   x      = (const float*)d_in[0];
    const int32_t* pw     = (const int32_t*)d_in[1];
    const float*   scales = (const float*)d_in[2];
    const float*   bias   = (const float*)d_in[3];
    float*         out    = (float*)d_out;
    const int M = in_sizes[0] / KDIM;   // 8192

    const long long nx = (long long)M * KDIM;
    convert_x_kernel<<<(int)((nx / 8 + 255) / 256), 256>>>(x, nx);

    dequant_kernel<<<dim3(NDIM / 64, KDIM / 256), 256>>>(pw, scales);

    const int smem_bytes = STAGES * (A_STG + B_STG) * (int)sizeof(__half);  // 208896
    cudaFuncSetAttribute(gemm_kernel, cudaFuncAttributeMaxDynamicSharedMemorySize,
                         smem_bytes);
    const int grid = (M / BM) * (NDIM / BN);
    gemm_kernel<<<grid, 256, smem_bytes>>>(bias, out, M);
}